// round 2
// baseline (speedup 1.0000x reference)
#include <cuda_runtime.h>
#include <math.h>

#define BB 64
#define SS 512
#define HID 40
#define HEADS 4
#define DH 10
#define INTER 20
#define TT (BB*SS)

// scratch (allocation-free rule: __device__ globals)
__device__ __align__(16) float g_q[BB*HEADS*SS*DH];
__device__ __align__(16) float g_k[BB*HEADS*SS*DH];
__device__ __align__(16) float g_v[BB*HEADS*SS*DH];
__device__ __align__(16) float g_ctx[TT*HID];
__device__ __align__(16) float g_attn_out_unused; // placeholder

__device__ __forceinline__ float ex2(float x){
    float y; asm("ex2.approx.f32 %0, %1;" : "=f"(y) : "f"(x)); return y;
}

// ---------------- Kernel 1: LN1 + QKV projection ----------------
// 128 tokens per block, 1 token per thread. Weights+x tile staged in SMEM.
__global__ void __launch_bounds__(128) k_ln_qkv(
    const float* __restrict__ x,
    const float* __restrict__ g1, const float* __restrict__ b1,
    const float* __restrict__ Wq, const float* __restrict__ bq,
    const float* __restrict__ Wk, const float* __restrict__ bk,
    const float* __restrict__ Wv, const float* __restrict__ bv)
{
    __shared__ float Ws[HID][3*HID];       // [i][o] : 0-39 q, 40-79 k, 80-119 v
    __shared__ float bs[3*HID];
    __shared__ float xs[128][HID+1];

    const int tid = threadIdx.x;
    const int t0  = blockIdx.x * 128;

    for (int idx = tid; idx < HID*HID; idx += 128) {
        int i = idx / HID, o = idx % HID;
        Ws[i][o]         = Wq[idx];
        Ws[i][HID+o]     = Wk[idx];
        Ws[i][2*HID+o]   = Wv[idx];
    }
    if (tid < HID) { bs[tid] = bq[tid]; bs[HID+tid] = bk[tid]; bs[2*HID+tid] = bv[tid]; }
    for (int idx = tid; idx < 128*HID; idx += 128)
        xs[idx/HID][idx%HID] = x[t0*HID + idx];
    __syncthreads();

    const int t = t0 + tid;
    const int b = t / SS, s = t % SS;

    float h[HID];
    float mu = 0.f;
#pragma unroll
    for (int i = 0; i < HID; i++) { h[i] = xs[tid][i]; mu += h[i]; }
    mu *= (1.f/HID);
    float var = 0.f;
#pragma unroll
    for (int i = 0; i < HID; i++) { float d = h[i]-mu; var += d*d; }
    var *= (1.f/HID);
    float rs = rsqrtf(var + 1e-5f);
#pragma unroll
    for (int i = 0; i < HID; i++)
        h[i] = (h[i]-mu)*rs*__ldg(&g1[i]) + __ldg(&b1[i]);

    for (int og = 0; og < 3*HID; og += 4) {
        float4 a = *(const float4*)&bs[og];
#pragma unroll
        for (int i = 0; i < HID; i++) {
            float4 w = *(const float4*)&Ws[i][og];
            a.x = fmaf(h[i], w.x, a.x);
            a.y = fmaf(h[i], w.y, a.y);
            a.z = fmaf(h[i], w.z, a.z);
            a.w = fmaf(h[i], w.w, a.w);
        }
        float av[4] = {a.x, a.y, a.z, a.w};
#pragma unroll
        for (int j = 0; j < 4; j++) {
            int o = og + j;
            int which = o / HID;        // 0=q 1=k 2=v
            int oo = o % HID;
            int hh = oo / DH, d = oo % DH;
            float* dst = (which == 0) ? g_q : (which == 1) ? g_k : g_v;
            dst[((b*HEADS + hh)*SS + s)*DH + d] = av[j];
        }
    }
}

// ---------------- Kernel 2: flash attention ----------------
// grid = B*HEADS*4 blocks; block = 128 threads; thread = one (query,head).
// K,V tile [S,DH] for this (b,h) resident in SMEM (contiguous in [B,H,S,DH]).
__global__ void __launch_bounds__(128) k_attn()
{
    __shared__ float ks[SS*DH];
    __shared__ float vs[SS*DH];

    const int tid = threadIdx.x;
    const int bh  = blockIdx.x >> 2;    // 0..255
    const int qt  = blockIdx.x & 3;
    const int b   = bh >> 2, hh = bh & 3;

    const float* kbase = g_k + bh*SS*DH;
    const float* vbase = g_v + bh*SS*DH;
    for (int idx = tid; idx < SS*DH/4; idx += 128) {
        ((float4*)ks)[idx] = ((const float4*)kbase)[idx];
        ((float4*)vs)[idx] = ((const float4*)vbase)[idx];
    }

    const int qi = qt*128 + tid;
    // fold 1/sqrt(DH) and log2(e) into q so inner loop uses ex2 directly
    const float scale = 0.316227766016838f * 1.44269504088896f;
    float qr[DH];
    const float* qp = g_q + (bh*SS + qi)*DH;
#pragma unroll
    for (int d = 0; d < DH; d++) qr[d] = qp[d] * scale;
    __syncthreads();

    float m = -1e30f, l = 0.f;
    float acc[DH];
#pragma unroll
    for (int d = 0; d < DH; d++) acc[d] = 0.f;

#pragma unroll 4
    for (int s = 0; s < SS; s++) {
        const float2* kk = (const float2*)&ks[s*DH];
        float dot = 0.f;
#pragma unroll
        for (int d2 = 0; d2 < 5; d2++) {
            float2 kv = kk[d2];
            dot = fmaf(qr[2*d2], kv.x, dot);
            dot = fmaf(qr[2*d2+1], kv.y, dot);
        }
        if (dot > m) {                       // rare after warmup
            float c = ex2(m - dot);
            l *= c;
#pragma unroll
            for (int d = 0; d < DH; d++) acc[d] *= c;
            m = dot;
        }
        float p = ex2(dot - m);
        l += p;
        const float2* vv = (const float2*)&vs[s*DH];
#pragma unroll
        for (int d2 = 0; d2 < 5; d2++) {
            float2 v2 = vv[d2];
            acc[2*d2]   = fmaf(p, v2.x, acc[2*d2]);
            acc[2*d2+1] = fmaf(p, v2.y, acc[2*d2+1]);
        }
    }

    float inv = 1.f / l;
    float* cp = g_ctx + ((b*SS + qi)*HID) + hh*DH;
#pragma unroll
    for (int d = 0; d < DH; d++) cp[d] = acc[d] * inv;
}

// ---------------- Kernel 3: Wo + residual + LN2 + FFN + residual ----------------
__global__ void __launch_bounds__(128) k_out_ffn(
    const float* __restrict__ x,
    const float* __restrict__ Wo, const float* __restrict__ bo,
    const float* __restrict__ g2, const float* __restrict__ b2g,
    const float* __restrict__ W1, const float* __restrict__ b1f,
    const float* __restrict__ W2, const float* __restrict__ b2f,
    float* __restrict__ out)
{
    __shared__ float Wos[HID*HID];     // [i][o]
    __shared__ float W1s[HID*INTER];   // [i][o]
    __shared__ float W2s[INTER*HID];   // [i][o]
    __shared__ float bos[HID], b1s[INTER], b2s[HID];

    const int tid = threadIdx.x;
    for (int i = tid; i < HID*HID; i += 128)   Wos[i] = Wo[i];
    for (int i = tid; i < HID*INTER; i += 128) W1s[i] = W1[i];
    for (int i = tid; i < INTER*HID; i += 128) W2s[i] = W2[i];
    if (tid < HID)   { bos[tid] = bo[tid]; b2s[tid] = b2f[tid]; }
    if (tid < INTER) { b1s[tid] = b1f[tid]; }
    __syncthreads();

    const int t = blockIdx.x*128 + tid;

    float c[HID];
#pragma unroll
    for (int i = 0; i < HID; i++) c[i] = g_ctx[t*HID + i];

    // attn_out = ctx @ Wo + bo + x
    float ao[HID];
    for (int og = 0; og < HID; og += 4) {
        float4 a = *(const float4*)&bos[og];
#pragma unroll
        for (int i = 0; i < HID; i++) {
            float4 w = *(const float4*)&Wos[i*HID + og];
            a.x = fmaf(c[i], w.x, a.x);
            a.y = fmaf(c[i], w.y, a.y);
            a.z = fmaf(c[i], w.z, a.z);
            a.w = fmaf(c[i], w.w, a.w);
        }
        ao[og]   = a.x + x[t*HID + og];
        ao[og+1] = a.y + x[t*HID + og+1];
        ao[og+2] = a.z + x[t*HID + og+2];
        ao[og+3] = a.w + x[t*HID + og+3];
    }

    // LN2 (reuse c[] for normalized h2)
    float mu = 0.f;
#pragma unroll
    for (int i = 0; i < HID; i++) mu += ao[i];
    mu *= (1.f/HID);
    float var = 0.f;
#pragma unroll
    for (int i = 0; i < HID; i++) { float d = ao[i]-mu; var += d*d; }
    var *= (1.f/HID);
    float rs = rsqrtf(var + 1e-5f);
#pragma unroll
    for (int i = 0; i < HID; i++)
        c[i] = (ao[i]-mu)*rs*__ldg(&g2[i]) + __ldg(&b2g[i]);

    // inter = gelu(h2 @ W1 + b1)   (exact gelu: erf)
    float it[INTER];
    for (int og = 0; og < INTER; og += 4) {
        float4 a = *(const float4*)&b1s[og];
#pragma unroll
        for (int i = 0; i < HID; i++) {
            float4 w = *(const float4*)&W1s[i*INTER + og];
            a.x = fmaf(c[i], w.x, a.x);
            a.y = fmaf(c[i], w.y, a.y);
            a.z = fmaf(c[i], w.z, a.z);
            a.w = fmaf(c[i], w.w, a.w);
        }
        float av[4] = {a.x, a.y, a.z, a.w};
#pragma unroll
        for (int j = 0; j < 4; j++) {
            float z = av[j];
            it[og+j] = 0.5f * z * (1.f + erff(z * 0.70710678118654752f));
        }
    }

    // out = inter @ W2 + b2 + attn_out
    for (int og = 0; og < HID; og += 4) {
        float4 a = *(const float4*)&b2s[og];
#pragma unroll
        for (int i = 0; i < INTER; i++) {
            float4 w = *(const float4*)&W2s[i*HID + og];
            a.x = fmaf(it[i], w.x, a.x);
            a.y = fmaf(it[i], w.y, a.y);
            a.z = fmaf(it[i], w.z, a.z);
            a.w = fmaf(it[i], w.w, a.w);
        }
        out[t*HID + og]   = a.x + ao[og];
        out[t*HID + og+1] = a.y + ao[og+1];
        out[t*HID + og+2] = a.z + ao[og+2];
        out[t*HID + og+3] = a.w + ao[og+3];
    }
}

extern "C" void kernel_launch(void* const* d_in, const int* in_sizes, int n_in,
                              void* d_out, int out_size)
{
    const float* x    = (const float*)d_in[0];
    const float* ln1g = (const float*)d_in[1];
    const float* ln1b = (const float*)d_in[2];
    const float* Wq   = (const float*)d_in[3];
    const float* bq   = (const float*)d_in[4];
    const float* Wk   = (const float*)d_in[5];
    const float* bk   = (const float*)d_in[6];
    const float* Wv   = (const float*)d_in[7];
    const float* bv   = (const float*)d_in[8];
    const float* Wo   = (const float*)d_in[9];
    const float* bo   = (const float*)d_in[10];
    const float* ln2g = (const float*)d_in[11];
    const float* ln2b = (const float*)d_in[12];
    const float* W1   = (const float*)d_in[13];
    const float* b1   = (const float*)d_in[14];
    const float* W2   = (const float*)d_in[15];
    const float* b2   = (const float*)d_in[16];
    float* out = (float*)d_out;

    k_ln_qkv<<<TT/128, 128>>>(x, ln1g, ln1b, Wq, bq, Wk, bk, Wv, bv);
    k_attn<<<BB*HEADS*4, 128>>>();
    k_out_ffn<<<TT/128, 128>>>(x, Wo, bo, ln2g, ln2b, W1, b1, W2, b2, out);
}